// round 1
// baseline (speedup 1.0000x reference)
#include <cuda_runtime.h>

// SeparateLoss: mean over the N x N cosine-similarity matrix masked by
// label inequality. For binary labels this is exactly (2/N^2) * dot(S0, S1)
// where Sk = sum of normalized feature rows with label k.
//
// Shapes: feat [4, 64, 128, 128] f32, label [4, 1, 128, 128] i32.
// Nearest-resize to 64x64 picks even indices: (i*128)//64 = 2i.
// N = 4*64*64 = 16384, C = 64.

#define B 4
#define C 64
#define H 128
#define W 128
#define X 64                      // output spatial size
#define NBLK (B * X)              // 256 blocks in pass 1
#define NTOT 16384.0f             // N

__device__ float g_partial[NBLK * 2 * C];   // [blk][class][ch], fully rewritten each launch

__global__ void __launch_bounds__(256) separate_pass1(
    const float* __restrict__ feat, const int* __restrict__ label)
{
    __shared__ float sm[C * 65];   // [ch][xi], padded row to kill bank conflicts
    __shared__ float invn[X];
    __shared__ int   lab[X];

    const int b   = blockIdx.y;
    const int yi  = blockIdx.x;
    const int y   = yi * 2;       // nearest-neighbor source row
    const int tid = threadIdx.x;

    const float* fb = feat + (size_t)b * C * H * W + (size_t)y * W;

    // Stage tile: 64 channels x 64 x-positions (x = 2*xi)
    #pragma unroll
    for (int i = tid; i < C * X; i += 256) {
        const int ch = i >> 6;
        const int xi = i & 63;
        sm[ch * 65 + xi] = fb[(size_t)ch * (H * W) + xi * 2];
    }
    if (tid < X) lab[tid] = label[b * (H * W) + y * W + tid * 2];
    __syncthreads();

    // Per-position inverse L2 norm (torch F.normalize: x / max(||x||, eps))
    if (tid < X) {
        float s = 0.f;
        #pragma unroll
        for (int ch = 0; ch < C; ch++) {
            const float v = sm[ch * 65 + tid];
            s += v * v;
        }
        invn[tid] = 1.0f / fmaxf(sqrtf(s), 1e-12f);
    }
    __syncthreads();

    // Per-channel class sums over the 64 positions of this row
    if (tid < C) {
        float s0 = 0.f, s1 = 0.f;
        #pragma unroll
        for (int xi = 0; xi < X; xi++) {
            const float v = sm[tid * 65 + xi] * invn[xi];
            if (lab[xi] == 0) s0 += v; else s1 += v;
        }
        const int blk = b * X + yi;
        g_partial[blk * (2 * C) + tid]     = s0;
        g_partial[blk * (2 * C) + C + tid] = s1;
    }
}

__global__ void __launch_bounds__(128) separate_pass2(float* __restrict__ out)
{
    __shared__ float S[2 * C];
    const int t = threadIdx.x;

    // Deterministic reduction over the 256 block partials
    float s = 0.f;
    #pragma unroll 8
    for (int blk = 0; blk < NBLK; blk++)
        s += g_partial[blk * (2 * C) + t];
    S[t] = s;
    __syncthreads();

    if (t < 32) {
        // dot(S0, S1): each lane covers channels t and t+32
        float p = S[t] * S[C + t] + S[t + 32] * S[C + t + 32];
        #pragma unroll
        for (int o = 16; o > 0; o >>= 1)
            p += __shfl_down_sync(0xffffffffu, p, o);
        if (t == 0)
            out[0] = p * (2.0f / (NTOT * NTOT));
    }
}

extern "C" void kernel_launch(void* const* d_in, const int* in_sizes, int n_in,
                              void* d_out, int out_size)
{
    const float* feat  = (const float*)d_in[0];
    const int*   label = (const int*)d_in[1];
    float*       out   = (float*)d_out;

    (void)in_sizes; (void)n_in; (void)out_size;

    separate_pass1<<<dim3(X, B), 256>>>(feat, label);
    separate_pass2<<<1, 128>>>(out);
}